// round 10
// baseline (speedup 1.0000x reference)
#include <cuda_runtime.h>
#include <cuda_bf16.h>
#include <math.h>
#include <stdint.h>

// Problem constants
#define BB 64
#define SS 256
#define II 512
#define HH 512
#define GCOLS (4*HH)          // 2048 gate-columns per direction (i,f,g,o)

// ---------------------------------------------------------------------------
// Scratch (device globals: allocation-free rule)
// ---------------------------------------------------------------------------
__device__ float g_gx[2][SS][GCOLS][BB];          // 256 MB: gx[d][t][gatecol][b]
// Double-buffered hidden state, bf16 hi/lo splits: [d][parity][split][b][k]
__device__ __align__(16) __nv_bfloat16 g_hbf[2][2][2][BB][HH];
// Init barrier (atomic, replay-safe: gen read dynamically)
__device__ unsigned g_bar_count[2];
__device__ unsigned g_bar_gen[2];
// Step barrier v2: per-block flags (32B stride) + go word, reset each launch
__device__ unsigned g_flag[2][64 * 8];
__device__ unsigned g_go[2];

// bf16 split operands for the tensor-core projection
__device__ __align__(16) __nv_bfloat16 g_xhi[BB * SS * II];      // x hi
__device__ __align__(16) __nv_bfloat16 g_xlo[BB * SS * II];      // x residual
__device__ __align__(16) __nv_bfloat16 g_wthi[2 * 4 * HH * II];  // W^T (input part) hi: [d][g][c][k]
__device__ __align__(16) __nv_bfloat16 g_wtlo[2 * 4 * HH * II];  // W^T lo

struct Ptrs {
    const float* W[2][4];     // [dir][gate: i,f,g(c),o]  shape (I+H, H) row-major
    const float* bias[2][4];  // (H,)
};

// ---------------------------------------------------------------------------
// Helpers
// ---------------------------------------------------------------------------
__device__ __forceinline__ void mma16816(float* c, const uint32_t* a, const uint32_t* b)
{
    asm volatile(
        "mma.sync.aligned.m16n8k16.row.col.f32.bf16.bf16.f32 "
        "{%0,%1,%2,%3}, {%4,%5,%6,%7}, {%8,%9}, {%0,%1,%2,%3};\n"
        : "+f"(c[0]), "+f"(c[1]), "+f"(c[2]), "+f"(c[3])
        : "r"(a[0]), "r"(a[1]), "r"(a[2]), "r"(a[3]), "r"(b[0]), "r"(b[1]));
}

__device__ __forceinline__ void cp_async16(uint32_t smem_addr, const void* gptr)
{
    asm volatile("cp.async.cg.shared.global [%0], [%1], 16;"
                 :: "r"(smem_addr), "l"(gptr) : "memory");
}
#define CP_COMMIT() asm volatile("cp.async.commit_group;" ::: "memory")
#define CP_WAIT0()  asm volatile("cp.async.wait_group 0;" ::: "memory")
#define CP_WAIT1()  asm volatile("cp.async.wait_group 1;" ::: "memory")

__device__ __forceinline__ unsigned ldg_acq(unsigned* p) {
    unsigned v;
    asm volatile("ld.acquire.gpu.u32 %0, [%1];" : "=r"(v) : "l"(p) : "memory");
    return v;
}
__device__ __forceinline__ unsigned ld_rlx(unsigned* p) {
    unsigned v;
    asm volatile("ld.relaxed.gpu.u32 %0, [%1];" : "=r"(v) : "l"(p) : "memory");
    return v;
}
__device__ __forceinline__ unsigned atom_add_rel(unsigned* p, unsigned v) {
    unsigned o;
    asm volatile("atom.add.release.gpu.u32 %0, [%1], %2;" : "=r"(o) : "l"(p), "r"(v) : "memory");
    return o;
}
__device__ __forceinline__ void st_rel(unsigned* p, unsigned v) {
    asm volatile("st.release.gpu.u32 [%0], %1;" :: "l"(p), "r"(v) : "memory");
}
__device__ __forceinline__ void st_rlx(unsigned* p, unsigned v) {
    asm volatile("st.relaxed.gpu.u32 [%0], %1;" :: "l"(p), "r"(v) : "memory");
}
#define FENCE_ACQREL() asm volatile("fence.acq_rel.gpu;" ::: "memory")

__device__ __forceinline__ float fsigmoid(float x) {
    x = fminf(fmaxf(x, -30.f), 30.f);
    float e = __expf(-x);
    return __fdividef(1.f, 1.f + e);
}
__device__ __forceinline__ float ftanh_(float x) {
    x = fminf(fmaxf(x, -15.f), 15.f);
    float e = __expf(-2.f * x);
    return __fdividef(1.f - e, 1.f + e);
}

// ---------------------------------------------------------------------------
// Split kernels: build bf16 hi/lo operands
// ---------------------------------------------------------------------------
__global__ void split_x_kernel(const float* __restrict__ x)
{
    int n = BB * SS * II;
    for (int i = blockIdx.x * blockDim.x + threadIdx.x; i < n; i += gridDim.x * blockDim.x) {
        float v = x[i];
        __nv_bfloat16 hi = __float2bfloat16(v);
        g_xhi[i] = hi;
        g_xlo[i] = __float2bfloat16(v - __bfloat162float(hi));
    }
}

__global__ void split_wt_kernel(Ptrs p)
{
    __shared__ float tile[32][33];
    const int dg = blockIdx.z;           // 0..7
    const int d  = dg >> 2;
    const int g  = dg & 3;
    const int k0 = blockIdx.x * 32;
    const int c0 = blockIdx.y * 32;
    const int tid = threadIdx.x;         // 256
    const int tx = tid & 31;
    const int ty = tid >> 5;             // 0..7

    const float* W = p.W[d][g];
#pragma unroll
    for (int r = 0; r < 4; r++) {
        int k = ty + r * 8;
        tile[k][tx] = W[(size_t)(k0 + k) * HH + c0 + tx];
    }
    __syncthreads();
#pragma unroll
    for (int r = 0; r < 4; r++) {
        int c = ty + r * 8;
        float v = tile[tx][c];
        __nv_bfloat16 hi = __float2bfloat16(v);
        size_t idx = ((size_t)(dg) * HH + c0 + c) * II + k0 + tx;
        g_wthi[idx] = hi;
        g_wtlo[idx] = __float2bfloat16(v - __bfloat162float(hi));
    }
}

// ---------------------------------------------------------------------------
// Kernel A: tensor-core input projection via mma.sync (bf16-split, 3 terms)
// cp.async double-buffered staging (unchanged from round 9 PASS)
// ---------------------------------------------------------------------------
#define PSTR 40                 // padded SMEM k-stride (bf16 units)
#define PJ_T (128 * PSTR)       // elems per (buf,split) tile
#define PJ_SMEM_BYTES (8 * PJ_T * 2)   // 81920 B

__global__ void __launch_bounds__(256, 2) proj_mma_kernel(Ptrs p)
{
    extern __shared__ __nv_bfloat16 psm[];
    __nv_bfloat16* Ab = psm;
    __nv_bfloat16* Bb = psm + 4 * PJ_T;
    const uint32_t smbA = (uint32_t)__cvta_generic_to_shared(Ab);
    const uint32_t smbB = (uint32_t)__cvta_generic_to_shared(Bb);

    const int tid  = threadIdx.x;
    const int lane = tid & 31;
    const int wid  = tid >> 5;
    const int wm   = wid >> 2;          // 0..1 (M)
    const int wn   = wid & 3;           // 0..3 (N)
    const int r    = lane >> 2;         // 0..7
    const int qc   = lane & 3;          // 0..3

    const int ct   = blockIdx.x;        // 0..15
    const int tg   = blockIdx.y;        // 0..127
    const int d    = blockIdx.z;
    const int gate = ct >> 2;
    const int hb   = (ct & 3) * 128;
    const int t0   = tg * 2;

    const __nv_bfloat16* __restrict__ wthi = &g_wthi[((size_t)(d * 4 + gate) * HH + hb) * II];
    const __nv_bfloat16* __restrict__ wtlo = &g_wtlo[((size_t)(d * 4 + gate) * HH + hb) * II];

    float acc[4][4][4];
#pragma unroll
    for (int mt = 0; mt < 4; mt++)
#pragma unroll
        for (int nt = 0; nt < 4; nt++)
#pragma unroll
            for (int u = 0; u < 4; u++) acc[mt][nt][u] = 0.f;

    auto stage = [&](int ch, int buf) {
        const int k0 = ch * 32;
#pragma unroll
        for (int it = 0; it < 2; it++) {
            int q   = tid + it * 256;
            int row = q >> 2;
            int sl  = (q & 3) * 8;
            size_t src = (size_t)row * II + k0 + sl;
            cp_async16(smbA + (uint32_t)(((buf * 2 + 0) * PJ_T) + row * PSTR + sl) * 2u, wthi + src);
            cp_async16(smbA + (uint32_t)(((buf * 2 + 1) * PJ_T) + row * PSTR + sl) * 2u, wtlo + src);
        }
#pragma unroll
        for (int it = 0; it < 2; it++) {
            int q   = tid + it * 256;
            int row = q >> 2;
            int sl  = (q & 3) * 8;
            int b   = row & 63;
            int tl  = row >> 6;
            size_t src = ((size_t)b * SS + t0 + tl) * II + k0 + sl;
            cp_async16(smbB + (uint32_t)(((buf * 2 + 0) * PJ_T) + row * PSTR + sl) * 2u, &g_xhi[src]);
            cp_async16(smbB + (uint32_t)(((buf * 2 + 1) * PJ_T) + row * PSTR + sl) * 2u, &g_xlo[src]);
        }
        CP_COMMIT();
    };

    stage(0, 0);
    int buf = 0;
    for (int ch = 0; ch < 16; ch++) {
        if (ch < 15) { stage(ch + 1, buf ^ 1); CP_WAIT1(); }
        else         { CP_WAIT0(); }
        __syncthreads();

        const __nv_bfloat16* As0 = Ab + (buf * 2 + 0) * PJ_T;
        const __nv_bfloat16* As1 = Ab + (buf * 2 + 1) * PJ_T;
        const __nv_bfloat16* Bs0 = Bb + (buf * 2 + 0) * PJ_T;
        const __nv_bfloat16* Bs1 = Bb + (buf * 2 + 1) * PJ_T;

#pragma unroll
        for (int s = 0; s < 2; s++) {
            const int kb = s * 16;
            uint32_t bh[4][2], bl[4][2];
#pragma unroll
            for (int nt = 0; nt < 4; nt++) {
                int n   = wn * 32 + nt * 8 + r;
                int off = n * PSTR + kb + qc * 2;
                bh[nt][0] = *(const uint32_t*)&Bs0[off];
                bh[nt][1] = *(const uint32_t*)&Bs0[off + 8];
                bl[nt][0] = *(const uint32_t*)&Bs1[off];
                bl[nt][1] = *(const uint32_t*)&Bs1[off + 8];
            }
#pragma unroll
            for (int mt = 0; mt < 4; mt++) {
                int m   = wm * 64 + mt * 16 + r;
                int off = m * PSTR + kb + qc * 2;
                uint32_t ah[4], al[4];
                ah[0] = *(const uint32_t*)&As0[off];
                ah[1] = *(const uint32_t*)&As0[off + 8 * PSTR];
                ah[2] = *(const uint32_t*)&As0[off + 8];
                ah[3] = *(const uint32_t*)&As0[off + 8 * PSTR + 8];
                al[0] = *(const uint32_t*)&As1[off];
                al[1] = *(const uint32_t*)&As1[off + 8 * PSTR];
                al[2] = *(const uint32_t*)&As1[off + 8];
                al[3] = *(const uint32_t*)&As1[off + 8 * PSTR + 8];
#pragma unroll
                for (int nt = 0; nt < 4; nt++) {
                    mma16816(acc[mt][nt], ah, bh[nt]);   // hi*hi
                    mma16816(acc[mt][nt], ah, bl[nt]);   // hi*lo
                    mma16816(acc[mt][nt], al, bh[nt]);   // lo*hi
                }
            }
        }
        __syncthreads();
        buf ^= 1;
    }

    const float* __restrict__ bias = p.bias[d][gate];
#pragma unroll
    for (int mt = 0; mt < 4; mt++) {
        int col0 = hb + wm * 64 + mt * 16 + r;
        float bv0 = bias[col0];
        float bv1 = bias[col0 + 8];
#pragma unroll
        for (int nt = 0; nt < 4; nt++) {
            int n  = wn * 32 + nt * 8 + qc * 2;
            int tl = n >> 6;
            int b  = n & 63;
            float2 v0, v1;
            v0.x = acc[mt][nt][0] + bv0;
            v0.y = acc[mt][nt][1] + bv0;
            v1.x = acc[mt][nt][2] + bv1;
            v1.y = acc[mt][nt][3] + bv1;
            *(float2*)&g_gx[d][t0 + tl][gate * 512 + col0][b]     = v0;
            *(float2*)&g_gx[d][t0 + tl][gate * 512 + col0 + 8][b] = v1;
        }
    }
}

// ---------------------------------------------------------------------------
// Init grid barrier (atomic; replay-safe). Used once per launch.
// ---------------------------------------------------------------------------
__device__ __forceinline__ void grid_barrier_init(int id)
{
    __syncthreads();
    if (threadIdx.x == 0) {
        unsigned gen = ldg_acq(&g_bar_gen[id]);
        unsigned old = atom_add_rel(&g_bar_count[id], 1u);
        if (old == 63u) {
            st_rlx(&g_bar_count[id], 0u);
            st_rel(&g_bar_gen[id], gen + 1u);
        } else {
            while (ldg_acq(&g_bar_gen[id]) == gen) { __nanosleep(32); }
        }
    }
    __syncthreads();
}

// ---------------------------------------------------------------------------
// Kernel B: persistent tensor-core recurrent kernel, v4.
// - A (W) fragments in registers; 8 warps = 2M x 2N x 2K split-K.
// - Flag-array step barrier (parallel arrival stores, monotonic gens).
// - gx prefetched one step ahead (double buffer, staged by k-group 0 only).
// - Merged split-K reduce: gateA (wk0, +gx) + gateB (wk1); cell adds both.
// ---------------------------------------------------------------------------
#define RWSTR 520
#define RB_HHI   0
#define RB_HLO   66560
#define RB_GA    133120
#define RB_GB    141568
#define RB_C     150016
#define RB_GX0   152064
#define RB_GX1   160256
#define RB_SMEM_BYTES 168448

__global__ void __launch_bounds__(256, 1) lstm_rec_mma_kernel(float* __restrict__ out, Ptrs p)
{
    const int blk = blockIdx.x;
    const int d   = blk >> 6;
    const int z   = blk & 63;
    const int hs0 = z * 8;
    const int tid = threadIdx.x;
    const int lane = tid & 31;
    const int wid  = tid >> 5;
    const int wm   = wid & 1;           // M half
    const int wn   = (wid >> 1) & 1;    // N half
    const int wk   = wid >> 2;          // K half
    const int r    = lane >> 2;
    const int qc   = lane & 3;

    extern __shared__ char smraw[];
    __nv_bfloat16* h_hi = (__nv_bfloat16*)(smraw + RB_HHI);
    __nv_bfloat16* h_lo = (__nv_bfloat16*)(smraw + RB_HLO);
    float* gateA = (float*)(smraw + RB_GA);       // [32][66] (wk0: acc + gx)
    float* gateB = (float*)(smraw + RB_GB);       // [32][66] (wk1: acc)
    float* c_sm  = (float*)(smraw + RB_C);        // [512]
    float* gx0   = (float*)(smraw + RB_GX0);      // [32][64]
    float* gx1   = (float*)(smraw + RB_GX1);      // [32][64]

    // --- Init: reset step-barrier state (replay safety) ---
    if (tid == 0) {
        st_rlx(&g_flag[d][z * 8], 0u);
        if (z == 0) st_rlx(&g_go[d], 0u);
    }

    // --- Init: stage W slice (bf16 hi/lo) into h region, preload A frags ---
    for (int i = tid; i < 32 * 512; i += 256) {
        int c = i >> 9;
        int k = i & 511;
        int g = c >> 3;
        int j = c & 7;
        float v = p.W[d][g][(size_t)(II + k) * HH + hs0 + j];
        __nv_bfloat16 hi = __float2bfloat16(v);
        h_hi[c * RWSTR + k] = hi;
        h_lo[c * RWSTR + k] = __float2bfloat16(v - __bfloat162float(hi));
    }
    __syncthreads();

    uint32_t ah[16][4], al[16][4];
    {
        const int mrow = wm * 16 + r;
        const int kbase = wk * 256;
#pragma unroll
        for (int ks = 0; ks < 16; ks++) {
            int off = mrow * RWSTR + kbase + ks * 16 + qc * 2;
            ah[ks][0] = *(const uint32_t*)&h_hi[off];
            ah[ks][1] = *(const uint32_t*)&h_hi[off + 8 * RWSTR];
            ah[ks][2] = *(const uint32_t*)&h_hi[off + 8];
            ah[ks][3] = *(const uint32_t*)&h_hi[off + 8 * RWSTR + 8];
            al[ks][0] = *(const uint32_t*)&h_lo[off];
            al[ks][1] = *(const uint32_t*)&h_lo[off + 8 * RWSTR];
            al[ks][2] = *(const uint32_t*)&h_lo[off + 8];
            al[ks][3] = *(const uint32_t*)&h_lo[off + 8 * RWSTR + 8];
        }
    }
    __syncthreads();   // h region now free

    const __nv_bfloat16 z16 = __float2bfloat16(0.f);
    for (int i = tid; i < 512; i += 256) {
        c_sm[i] = 0.f;
        int b = i >> 3;
        int j = i & 7;
        g_hbf[d][0][0][b][hs0 + j] = z16;
        g_hbf[d][0][1][b][hs0 + j] = z16;
    }
    grid_barrier_init(d);   // also publishes the flag/go resets

    const uint32_t smb_hhi = (uint32_t)__cvta_generic_to_shared(h_hi);
    const uint32_t smb_hlo = (uint32_t)__cvta_generic_to_shared(h_lo);
    const uint32_t smb_gx[2] = {
        (uint32_t)__cvta_generic_to_shared(gx0),
        (uint32_t)__cvta_generic_to_shared(gx1)
    };
    float* gxbuf[2] = { gx0, gx1 };

    // Prefetch gx for step 0 (k-group 0 only; 512 16B copies / 128 threads)
    if (wk == 0) {
        const int t0 = d ? (SS - 1) : 0;
#pragma unroll
        for (int it = 0; it < 4; it++) {
            int q  = tid + it * 128;
            int c  = q >> 4;
            int sl = (q & 15) * 4;
            int col = (c >> 3) * 512 + hs0 + (c & 7);
            cp_async16(smb_gx[0] + (uint32_t)(c * 64 + sl) * 4u, &g_gx[d][t0][col][sl]);
        }
        CP_COMMIT();
    }

    unsigned gen = 0;

    for (int s = 0; s < SS; s++) {
        const int t  = d ? (SS - 1 - s) : s;
        const int pr = s & 1;
        const int pw = pr ^ 1;
        const int buf = s & 1;
        const int gtid = tid & 127;

        // Stage h_hi then h_lo (own k-half) as two cp.async groups
#pragma unroll
        for (int it = 0; it < 16; it++) {
            int q   = gtid + it * 128;
            int row = q >> 5;
            int k8  = wk * 256 + (q & 31) * 8;
            cp_async16(smb_hhi + (uint32_t)(row * RWSTR + k8) * 2u, &g_hbf[d][pr][0][row][k8]);
        }
        CP_COMMIT();
#pragma unroll
        for (int it = 0; it < 16; it++) {
            int q   = gtid + it * 128;
            int row = q >> 5;
            int k8  = wk * 256 + (q & 31) * 8;
            cp_async16(smb_hlo + (uint32_t)(row * RWSTR + k8) * 2u, &g_hbf[d][pr][1][row][k8]);
        }
        CP_COMMIT();

        float acc[4][4];
#pragma unroll
        for (int nt = 0; nt < 4; nt++)
#pragma unroll
            for (int u = 0; u < 4; u++) acc[nt][u] = 0.f;

        const int kbase2 = wk * 256;

        // WAIT1: for wk0 drains {gx(s), h_hi}; for wk1 drains {h_hi}
        CP_WAIT1();
        asm volatile("bar.sync %0, 128;" :: "r"(1 + wk) : "memory");
        // pass 1: bh terms (hi*hi + lo*hi)
#pragma unroll
        for (int ks = 0; ks < 16; ks++) {
#pragma unroll
            for (int nt = 0; nt < 4; nt++) {
                const int n = wn * 32 + nt * 8 + r;
                const int boff = n * RWSTR + kbase2 + ks * 16 + qc * 2;
                uint32_t bh[2];
                bh[0] = *(const uint32_t*)&h_hi[boff];
                bh[1] = *(const uint32_t*)&h_hi[boff + 8];
                mma16816(acc[nt], ah[ks], bh);
                mma16816(acc[nt], al[ks], bh);
            }
        }
        CP_WAIT0();                          // h_lo ready
        asm volatile("bar.sync %0, 128;" :: "r"(1 + wk) : "memory");
        // pass 2: bl term (hi*lo)
#pragma unroll
        for (int ks = 0; ks < 16; ks++) {
#pragma unroll
            for (int nt = 0; nt < 4; nt++) {
                const int n = wn * 32 + nt * 8 + r;
                const int boff = n * RWSTR + kbase2 + ks * 16 + qc * 2;
                uint32_t bl[2];
                bl[0] = *(const uint32_t*)&h_lo[boff];
                bl[1] = *(const uint32_t*)&h_lo[boff + 8];
                mma16816(acc[nt], ah[ks], bl);
            }
        }

        // Prefetch gx(s+1) (k-group 0 only), overlaps gate/cell/barrier
        if (wk == 0 && s + 1 < SS) {
            const int tn = d ? (SS - 2 - s) : (s + 1);
#pragma unroll
            for (int it = 0; it < 4; it++) {
                int q  = tid + it * 128;
                int c  = q >> 4;
                int sl = (q & 15) * 4;
                int col = (c >> 3) * 512 + hs0 + (c & 7);
                cp_async16(smb_gx[buf ^ 1] + (uint32_t)(c * 64 + sl) * 4u, &g_gx[d][tn][col][sl]);
            }
            CP_COMMIT();
        }

        // Gate writes: wk0 -> gateA (acc + gx); wk1 -> gateB (acc)
        {
            const int c0r = wm * 16 + r;
            const int c1r = c0r + 8;
            float* gdst = wk ? gateB : gateA;
            const float* gsrc = gxbuf[buf];
#pragma unroll
            for (int nt = 0; nt < 4; nt++) {
                const int b0 = wn * 32 + nt * 8 + qc * 2;
                float2 o0, o1;
                if (wk == 0) {
                    float2 g0 = *(const float2*)&gsrc[c0r * 64 + b0];
                    float2 g1 = *(const float2*)&gsrc[c1r * 64 + b0];
                    o0.x = acc[nt][0] + g0.x;
                    o0.y = acc[nt][1] + g0.y;
                    o1.x = acc[nt][2] + g1.x;
                    o1.y = acc[nt][3] + g1.y;
                } else {
                    o0.x = acc[nt][0];
                    o0.y = acc[nt][1];
                    o1.x = acc[nt][2];
                    o1.y = acc[nt][3];
                }
                *(float2*)&gdst[c0r * 66 + b0] = o0;
                *(float2*)&gdst[c1r * 66 + b0] = o1;
            }
        }
        __syncthreads();

        // Cell update (adds both k-halves); publish h_t (bf16 hi/lo) + out
#pragma unroll
        for (int rr = 0; rr < 2; rr++) {
            int e  = tid + rr * 256;
            int b  = e >> 3;
            int j  = e & 7;
            float iv = gateA[(0 * 8 + j) * 66 + b] + gateB[(0 * 8 + j) * 66 + b];
            float fv = gateA[(1 * 8 + j) * 66 + b] + gateB[(1 * 8 + j) * 66 + b];
            float gv = gateA[(2 * 8 + j) * 66 + b] + gateB[(2 * 8 + j) * 66 + b];
            float ov = gateA[(3 * 8 + j) * 66 + b] + gateB[(3 * 8 + j) * 66 + b];
            iv = fsigmoid(iv);
            fv = fsigmoid(fv);
            ov = fsigmoid(ov);
            gv = ftanh_(gv);
            float cn = fv * c_sm[e] + iv * gv;
            c_sm[e] = cn;
            float hn = ov * ftanh_(cn);
            __nv_bfloat16 hi = __float2bfloat16(hn);
            g_hbf[d][pw][0][b][hs0 + j] = hi;
            g_hbf[d][pw][1][b][hs0 + j] = __float2bfloat16(hn - __bfloat162float(hi));
            out[((size_t)b * SS + t) * (2 * HH) + d * HH + hs0 + j] = hn;
        }

        // --- Step barrier v2: flag array + go word ---
        gen++;
        __syncthreads();
        if (tid == 0) {
            st_rel(&g_flag[d][z * 8], gen);
            if (z == 0) {
                for (;;) {
                    unsigned ok = 1u;
#pragma unroll
                    for (int i = 0; i < 64; i++)
                        ok &= (ld_rlx(&g_flag[d][i * 8]) >= gen) ? 1u : 0u;
                    if (ok) break;
                    __nanosleep(32);
                }
                FENCE_ACQREL();
                st_rel(&g_go[d], gen);
            } else {
                while (ld_rlx(&g_go[d]) < gen) { __nanosleep(32); }
                FENCE_ACQREL();
            }
        }
        __syncthreads();
    }
}

// ---------------------------------------------------------------------------
// Launch
// ---------------------------------------------------------------------------
extern "C" void kernel_launch(void* const* d_in, const int* in_sizes, int n_in,
                              void* d_out, int out_size)
{
    (void)in_sizes; (void)n_in; (void)out_size;
    const float* x = (const float*)d_in[0];

    Ptrs p;
    for (int d = 0; d < 2; d++)
        for (int g = 0; g < 4; g++) {
            p.W[d][g]    = (const float*)d_in[1 + d * 8 + 2 * g];
            p.bias[d][g] = (const float*)d_in[1 + d * 8 + 2 * g + 1];
        }

    cudaFuncSetAttribute(lstm_rec_mma_kernel,
                         cudaFuncAttributeMaxDynamicSharedMemorySize,
                         RB_SMEM_BYTES);
    cudaFuncSetAttribute(proj_mma_kernel,
                         cudaFuncAttributeMaxDynamicSharedMemorySize,
                         PJ_SMEM_BYTES);

    split_x_kernel<<<512, 256>>>(x);
    dim3 wgrid(16, 16, 8);
    split_wt_kernel<<<wgrid, 256>>>(p);

    dim3 pgrid(16, 128, 2);
    proj_mma_kernel<<<pgrid, 256, PJ_SMEM_BYTES>>>(p);

    lstm_rec_mma_kernel<<<128, 256, RB_SMEM_BYTES>>>((float*)d_out, p);
}

// round 11
// speedup vs baseline: 1.1393x; 1.1393x over previous
#include <cuda_runtime.h>
#include <cuda_bf16.h>
#include <math.h>
#include <stdint.h>

// Problem constants
#define BB 64
#define SS 256
#define II 512
#define HH 512
#define GCOLS (4*HH)          // 2048 gate-columns per direction (i,f,g,o)

// ---------------------------------------------------------------------------
// Scratch (device globals: allocation-free rule)
// ---------------------------------------------------------------------------
__device__ float g_gx[2][SS][GCOLS][BB];          // 256 MB: gx[d][t][gatecol][b]
// Double-buffered hidden state, bf16 hi/lo splits: [d][parity][split][b][k]
__device__ __align__(16) __nv_bfloat16 g_hbf[2][2][2][BB][HH];
__device__ unsigned g_bar_count[2];
__device__ unsigned g_bar_gen[2];

// bf16 split operands for the tensor-core projection
__device__ __align__(16) __nv_bfloat16 g_xhi[BB * SS * II];      // x hi
__device__ __align__(16) __nv_bfloat16 g_xlo[BB * SS * II];      // x residual
__device__ __align__(16) __nv_bfloat16 g_wthi[2 * 4 * HH * II];  // W^T (input part) hi: [d][g][c][k]
__device__ __align__(16) __nv_bfloat16 g_wtlo[2 * 4 * HH * II];  // W^T lo

struct Ptrs {
    const float* W[2][4];     // [dir][gate: i,f,g(c),o]  shape (I+H, H) row-major
    const float* bias[2][4];  // (H,)
};

// ---------------------------------------------------------------------------
// Helpers
// ---------------------------------------------------------------------------
__device__ __forceinline__ void mma16816(float* c, const uint32_t* a, const uint32_t* b)
{
    asm volatile(
        "mma.sync.aligned.m16n8k16.row.col.f32.bf16.bf16.f32 "
        "{%0,%1,%2,%3}, {%4,%5,%6,%7}, {%8,%9}, {%0,%1,%2,%3};\n"
        : "+f"(c[0]), "+f"(c[1]), "+f"(c[2]), "+f"(c[3])
        : "r"(a[0]), "r"(a[1]), "r"(a[2]), "r"(a[3]), "r"(b[0]), "r"(b[1]));
}

__device__ __forceinline__ void cp_async16(uint32_t smem_addr, const void* gptr)
{
    asm volatile("cp.async.cg.shared.global [%0], [%1], 16;"
                 :: "r"(smem_addr), "l"(gptr) : "memory");
}
#define CP_COMMIT() asm volatile("cp.async.commit_group;" ::: "memory")
#define CP_WAIT0()  asm volatile("cp.async.wait_group 0;" ::: "memory")
#define CP_WAIT1()  asm volatile("cp.async.wait_group 1;" ::: "memory")
#define CP_WAIT2()  asm volatile("cp.async.wait_group 2;" ::: "memory")

__device__ __forceinline__ unsigned ldg_acq(unsigned* p) {
    unsigned v;
    asm volatile("ld.acquire.gpu.u32 %0, [%1];" : "=r"(v) : "l"(p) : "memory");
    return v;
}
__device__ __forceinline__ unsigned atom_add_rel(unsigned* p, unsigned v) {
    unsigned o;
    asm volatile("atom.add.release.gpu.u32 %0, [%1], %2;" : "=r"(o) : "l"(p), "r"(v) : "memory");
    return o;
}
__device__ __forceinline__ void st_rel(unsigned* p, unsigned v) {
    asm volatile("st.release.gpu.u32 [%0], %1;" :: "l"(p), "r"(v) : "memory");
}
__device__ __forceinline__ void st_rlx(unsigned* p, unsigned v) {
    asm volatile("st.relaxed.gpu.u32 [%0], %1;" :: "l"(p), "r"(v) : "memory");
}

__device__ __forceinline__ float fsigmoid(float x) {
    x = fminf(fmaxf(x, -30.f), 30.f);
    float e = __expf(-x);
    return __fdividef(1.f, 1.f + e);
}
__device__ __forceinline__ float ftanh_(float x) {
    x = fminf(fmaxf(x, -15.f), 15.f);
    float e = __expf(-2.f * x);
    return __fdividef(1.f - e, 1.f + e);
}

// ---------------------------------------------------------------------------
// Split kernels: build bf16 hi/lo operands
// ---------------------------------------------------------------------------
__global__ void split_x_kernel(const float* __restrict__ x)
{
    int n = BB * SS * II;
    for (int i = blockIdx.x * blockDim.x + threadIdx.x; i < n; i += gridDim.x * blockDim.x) {
        float v = x[i];
        __nv_bfloat16 hi = __float2bfloat16(v);
        g_xhi[i] = hi;
        g_xlo[i] = __float2bfloat16(v - __bfloat162float(hi));
    }
}

__global__ void split_wt_kernel(Ptrs p)
{
    __shared__ float tile[32][33];
    const int dg = blockIdx.z;           // 0..7
    const int d  = dg >> 2;
    const int g  = dg & 3;
    const int k0 = blockIdx.x * 32;
    const int c0 = blockIdx.y * 32;
    const int tid = threadIdx.x;         // 256
    const int tx = tid & 31;
    const int ty = tid >> 5;             // 0..7

    const float* W = p.W[d][g];
#pragma unroll
    for (int r = 0; r < 4; r++) {
        int k = ty + r * 8;
        tile[k][tx] = W[(size_t)(k0 + k) * HH + c0 + tx];
    }
    __syncthreads();
#pragma unroll
    for (int r = 0; r < 4; r++) {
        int c = ty + r * 8;
        float v = tile[tx][c];
        __nv_bfloat16 hi = __float2bfloat16(v);
        size_t idx = ((size_t)(dg) * HH + c0 + c) * II + k0 + tx;
        g_wthi[idx] = hi;
        g_wtlo[idx] = __float2bfloat16(v - __bfloat162float(hi));
    }
}

// ---------------------------------------------------------------------------
// Kernel A: tensor-core input projection via mma.sync (bf16-split, 3 terms)
// cp.async double-buffered staging (unchanged from round 9 PASS)
// ---------------------------------------------------------------------------
#define PSTR 40                 // padded SMEM k-stride (bf16 units)
#define PJ_T (128 * PSTR)       // elems per (buf,split) tile
#define PJ_SMEM_BYTES (8 * PJ_T * 2)   // 81920 B

__global__ void __launch_bounds__(256, 2) proj_mma_kernel(Ptrs p)
{
    extern __shared__ __nv_bfloat16 psm[];
    __nv_bfloat16* Ab = psm;
    __nv_bfloat16* Bb = psm + 4 * PJ_T;
    const uint32_t smbA = (uint32_t)__cvta_generic_to_shared(Ab);
    const uint32_t smbB = (uint32_t)__cvta_generic_to_shared(Bb);

    const int tid  = threadIdx.x;
    const int lane = tid & 31;
    const int wid  = tid >> 5;
    const int wm   = wid >> 2;          // 0..1 (M)
    const int wn   = wid & 3;           // 0..3 (N)
    const int r    = lane >> 2;         // 0..7
    const int qc   = lane & 3;          // 0..3

    const int ct   = blockIdx.x;        // 0..15
    const int tg   = blockIdx.y;        // 0..127
    const int d    = blockIdx.z;
    const int gate = ct >> 2;
    const int hb   = (ct & 3) * 128;
    const int t0   = tg * 2;

    const __nv_bfloat16* __restrict__ wthi = &g_wthi[((size_t)(d * 4 + gate) * HH + hb) * II];
    const __nv_bfloat16* __restrict__ wtlo = &g_wtlo[((size_t)(d * 4 + gate) * HH + hb) * II];

    float acc[4][4][4];
#pragma unroll
    for (int mt = 0; mt < 4; mt++)
#pragma unroll
        for (int nt = 0; nt < 4; nt++)
#pragma unroll
            for (int u = 0; u < 4; u++) acc[mt][nt][u] = 0.f;

    auto stage = [&](int ch, int buf) {
        const int k0 = ch * 32;
#pragma unroll
        for (int it = 0; it < 2; it++) {
            int q   = tid + it * 256;
            int row = q >> 2;
            int sl  = (q & 3) * 8;
            size_t src = (size_t)row * II + k0 + sl;
            cp_async16(smbA + (uint32_t)(((buf * 2 + 0) * PJ_T) + row * PSTR + sl) * 2u, wthi + src);
            cp_async16(smbA + (uint32_t)(((buf * 2 + 1) * PJ_T) + row * PSTR + sl) * 2u, wtlo + src);
        }
#pragma unroll
        for (int it = 0; it < 2; it++) {
            int q   = tid + it * 256;
            int row = q >> 2;
            int sl  = (q & 3) * 8;
            int b   = row & 63;
            int tl  = row >> 6;
            size_t src = ((size_t)b * SS + t0 + tl) * II + k0 + sl;
            cp_async16(smbB + (uint32_t)(((buf * 2 + 0) * PJ_T) + row * PSTR + sl) * 2u, &g_xhi[src]);
            cp_async16(smbB + (uint32_t)(((buf * 2 + 1) * PJ_T) + row * PSTR + sl) * 2u, &g_xlo[src]);
        }
        CP_COMMIT();
    };

    stage(0, 0);
    int buf = 0;
    for (int ch = 0; ch < 16; ch++) {
        if (ch < 15) { stage(ch + 1, buf ^ 1); CP_WAIT1(); }
        else         { CP_WAIT0(); }
        __syncthreads();

        const __nv_bfloat16* As0 = Ab + (buf * 2 + 0) * PJ_T;
        const __nv_bfloat16* As1 = Ab + (buf * 2 + 1) * PJ_T;
        const __nv_bfloat16* Bs0 = Bb + (buf * 2 + 0) * PJ_T;
        const __nv_bfloat16* Bs1 = Bb + (buf * 2 + 1) * PJ_T;

#pragma unroll
        for (int s = 0; s < 2; s++) {
            const int kb = s * 16;
            uint32_t bh[4][2], bl[4][2];
#pragma unroll
            for (int nt = 0; nt < 4; nt++) {
                int n   = wn * 32 + nt * 8 + r;
                int off = n * PSTR + kb + qc * 2;
                bh[nt][0] = *(const uint32_t*)&Bs0[off];
                bh[nt][1] = *(const uint32_t*)&Bs0[off + 8];
                bl[nt][0] = *(const uint32_t*)&Bs1[off];
                bl[nt][1] = *(const uint32_t*)&Bs1[off + 8];
            }
#pragma unroll
            for (int mt = 0; mt < 4; mt++) {
                int m   = wm * 64 + mt * 16 + r;
                int off = m * PSTR + kb + qc * 2;
                uint32_t ah[4], al[4];
                ah[0] = *(const uint32_t*)&As0[off];
                ah[1] = *(const uint32_t*)&As0[off + 8 * PSTR];
                ah[2] = *(const uint32_t*)&As0[off + 8];
                ah[3] = *(const uint32_t*)&As0[off + 8 * PSTR + 8];
                al[0] = *(const uint32_t*)&As1[off];
                al[1] = *(const uint32_t*)&As1[off + 8 * PSTR];
                al[2] = *(const uint32_t*)&As1[off + 8];
                al[3] = *(const uint32_t*)&As1[off + 8 * PSTR + 8];
#pragma unroll
                for (int nt = 0; nt < 4; nt++) {
                    mma16816(acc[mt][nt], ah, bh[nt]);   // hi*hi
                    mma16816(acc[mt][nt], ah, bl[nt]);   // hi*lo
                    mma16816(acc[mt][nt], al, bh[nt]);   // lo*hi
                }
            }
        }
        __syncthreads();
        buf ^= 1;
    }

    const float* __restrict__ bias = p.bias[d][gate];
#pragma unroll
    for (int mt = 0; mt < 4; mt++) {
        int col0 = hb + wm * 64 + mt * 16 + r;
        float bv0 = bias[col0];
        float bv1 = bias[col0 + 8];
#pragma unroll
        for (int nt = 0; nt < 4; nt++) {
            int n  = wn * 32 + nt * 8 + qc * 2;
            int tl = n >> 6;
            int b  = n & 63;
            float2 v0, v1;
            v0.x = acc[mt][nt][0] + bv0;
            v0.y = acc[mt][nt][1] + bv0;
            v1.x = acc[mt][nt][2] + bv1;
            v1.y = acc[mt][nt][3] + bv1;
            *(float2*)&g_gx[d][t0 + tl][gate * 512 + col0][b]     = v0;
            *(float2*)&g_gx[d][t0 + tl][gate * 512 + col0 + 8][b] = v1;
        }
    }
}

// ---------------------------------------------------------------------------
// Grid barrier (release/acquire; nanosleep backoff) — round-9 version
// ---------------------------------------------------------------------------
__device__ __forceinline__ void grid_barrier(int id)
{
    __syncthreads();
    if (threadIdx.x == 0) {
        unsigned gen = ldg_acq(&g_bar_gen[id]);
        unsigned old = atom_add_rel(&g_bar_count[id], 1u);
        if (old == 63u) {
            st_rlx(&g_bar_count[id], 0u);
            st_rel(&g_bar_gen[id], gen + 1u);
        } else {
            while (ldg_acq(&g_bar_gen[id]) == gen) { __nanosleep(32); }
        }
    }
    __syncthreads();
}

// ---------------------------------------------------------------------------
// Kernel B: persistent tensor-core recurrent kernel, v3.1.
// Round-9 structure exactly, with ONE change: merged split-K reduce.
// wk0 writes gateA = acc + gx; wk1 writes gateB = acc; one __syncthreads;
// cell phase sums gateA + gateB. Removes red_sm round-trip + one barrier.
// ---------------------------------------------------------------------------
#define RWSTR 520
#define RB_HHI   0
#define RB_HLO   66560
#define RB_GA    133120
#define RB_GB    141568
#define RB_C     150016
#define RB_GXS   152064
#define RB_SMEM_BYTES 160256

__global__ void __launch_bounds__(256, 1) lstm_rec_mma_kernel(float* __restrict__ out, Ptrs p)
{
    const int blk = blockIdx.x;
    const int d   = blk >> 6;
    const int z   = blk & 63;
    const int hs0 = z * 8;
    const int tid = threadIdx.x;
    const int lane = tid & 31;
    const int wid  = tid >> 5;
    const int wm   = wid & 1;           // M half
    const int wn   = (wid >> 1) & 1;    // N half
    const int wk   = wid >> 2;          // K half
    const int r    = lane >> 2;
    const int qc   = lane & 3;

    extern __shared__ char smraw[];
    __nv_bfloat16* h_hi = (__nv_bfloat16*)(smraw + RB_HHI);
    __nv_bfloat16* h_lo = (__nv_bfloat16*)(smraw + RB_HLO);
    float* gateA = (float*)(smraw + RB_GA);       // [32][66] (wk0: acc + gx)
    float* gateB = (float*)(smraw + RB_GB);       // [32][66] (wk1: acc)
    float* c_sm  = (float*)(smraw + RB_C);        // [512]
    float* gxs   = (float*)(smraw + RB_GXS);      // [32][64]

    // --- Init: stage W slice (bf16 hi/lo) into h region, preload A frags ---
    {
        for (int i = tid; i < 32 * 512; i += 256) {
            int c = i >> 9;
            int k = i & 511;
            int g = c >> 3;
            int j = c & 7;
            float v = p.W[d][g][(size_t)(II + k) * HH + hs0 + j];
            __nv_bfloat16 hi = __float2bfloat16(v);
            h_hi[c * RWSTR + k] = hi;
            h_lo[c * RWSTR + k] = __float2bfloat16(v - __bfloat162float(hi));
        }
    }
    __syncthreads();

    uint32_t ah[16][4], al[16][4];
    {
        const int mrow = wm * 16 + r;
        const int kbase = wk * 256;
#pragma unroll
        for (int ks = 0; ks < 16; ks++) {
            int off = mrow * RWSTR + kbase + ks * 16 + qc * 2;
            ah[ks][0] = *(const uint32_t*)&h_hi[off];
            ah[ks][1] = *(const uint32_t*)&h_hi[off + 8 * RWSTR];
            ah[ks][2] = *(const uint32_t*)&h_hi[off + 8];
            ah[ks][3] = *(const uint32_t*)&h_hi[off + 8 * RWSTR + 8];
            al[ks][0] = *(const uint32_t*)&h_lo[off];
            al[ks][1] = *(const uint32_t*)&h_lo[off + 8 * RWSTR];
            al[ks][2] = *(const uint32_t*)&h_lo[off + 8];
            al[ks][3] = *(const uint32_t*)&h_lo[off + 8 * RWSTR + 8];
        }
    }
    __syncthreads();   // h region now free

    const __nv_bfloat16 z16 = __float2bfloat16(0.f);
    for (int i = tid; i < 512; i += 256) {
        c_sm[i] = 0.f;
        int b = i >> 3;
        int j = i & 7;
        g_hbf[d][0][0][b][hs0 + j] = z16;
        g_hbf[d][0][1][b][hs0 + j] = z16;
    }
    grid_barrier(d);

    const uint32_t smb_hhi = (uint32_t)__cvta_generic_to_shared(h_hi);
    const uint32_t smb_hlo = (uint32_t)__cvta_generic_to_shared(h_lo);
    const uint32_t smb_gxs = (uint32_t)__cvta_generic_to_shared(gxs);

    for (int s = 0; s < SS; s++) {
        const int t  = d ? (SS - 1 - s) : s;
        const int pr = s & 1;
        const int pw = pr ^ 1;
        const int gtid = tid & 127;

        // Group 1: h_hi (own k-half)
#pragma unroll
        for (int it = 0; it < 16; it++) {
            int q   = gtid + it * 128;       // 0..2047
            int row = q >> 5;
            int k8  = wk * 256 + (q & 31) * 8;
            cp_async16(smb_hhi + (uint32_t)(row * RWSTR + k8) * 2u, &g_hbf[d][pr][0][row][k8]);
        }
        CP_COMMIT();
        // Group 2: h_lo
#pragma unroll
        for (int it = 0; it < 16; it++) {
            int q   = gtid + it * 128;
            int row = q >> 5;
            int k8  = wk * 256 + (q & 31) * 8;
            cp_async16(smb_hlo + (uint32_t)(row * RWSTR + k8) * 2u, &g_hbf[d][pr][1][row][k8]);
        }
        CP_COMMIT();
        // Group 3: gx tile (fp32 32c x 64b), all threads
#pragma unroll
        for (int it = 0; it < 2; it++) {
            int q  = tid + it * 256;         // 0..511
            int c  = q >> 4;
            int sl = (q & 15) * 4;
            int col = (c >> 3) * 512 + hs0 + (c & 7);
            cp_async16(smb_gxs + (uint32_t)(c * 64 + sl) * 4u, &g_gx[d][t][col][sl]);
        }
        CP_COMMIT();

        float acc[4][4];
#pragma unroll
        for (int nt = 0; nt < 4; nt++)
#pragma unroll
            for (int u = 0; u < 4; u++) acc[nt][u] = 0.f;

        const int kbase2 = wk * 256;

        CP_WAIT2();                          // h_hi ready
        asm volatile("bar.sync %0, 128;" :: "r"(1 + wk) : "memory");
        // pass 1: bh terms (hi*hi + lo*hi)
#pragma unroll
        for (int ks = 0; ks < 16; ks++) {
#pragma unroll
            for (int nt = 0; nt < 4; nt++) {
                const int n = wn * 32 + nt * 8 + r;
                const int boff = n * RWSTR + kbase2 + ks * 16 + qc * 2;
                uint32_t bh[2];
                bh[0] = *(const uint32_t*)&h_hi[boff];
                bh[1] = *(const uint32_t*)&h_hi[boff + 8];
                mma16816(acc[nt], ah[ks], bh);
                mma16816(acc[nt], al[ks], bh);
            }
        }
        CP_WAIT1();                          // h_lo ready
        asm volatile("bar.sync %0, 128;" :: "r"(1 + wk) : "memory");
        // pass 2: bl term (hi*lo)
#pragma unroll
        for (int ks = 0; ks < 16; ks++) {
#pragma unroll
            for (int nt = 0; nt < 4; nt++) {
                const int n = wn * 32 + nt * 8 + r;
                const int boff = n * RWSTR + kbase2 + ks * 16 + qc * 2;
                uint32_t bl[2];
                bl[0] = *(const uint32_t*)&h_lo[boff];
                bl[1] = *(const uint32_t*)&h_lo[boff + 8];
                mma16816(acc[nt], ah[ks], bl);
            }
        }
        CP_WAIT0();                          // gx ready (everywhere)

        // Merged split-K: wk0 -> gateA (acc + gx); wk1 -> gateB (acc)
        {
            const int c0r = wm * 16 + r;
            const int c1r = c0r + 8;
            float* gdst = wk ? gateB : gateA;
#pragma unroll
            for (int nt = 0; nt < 4; nt++) {
                const int b0 = wn * 32 + nt * 8 + qc * 2;
                float2 o0, o1;
                if (wk == 0) {
                    float2 g0 = *(const float2*)&gxs[c0r * 64 + b0];
                    float2 g1 = *(const float2*)&gxs[c1r * 64 + b0];
                    o0.x = acc[nt][0] + g0.x;
                    o0.y = acc[nt][1] + g0.y;
                    o1.x = acc[nt][2] + g1.x;
                    o1.y = acc[nt][3] + g1.y;
                } else {
                    o0.x = acc[nt][0];
                    o0.y = acc[nt][1];
                    o1.x = acc[nt][2];
                    o1.y = acc[nt][3];
                }
                *(float2*)&gdst[c0r * 66 + b0] = o0;
                *(float2*)&gdst[c1r * 66 + b0] = o1;
            }
        }
        __syncthreads();

        // Cell update (adds both k-halves); publish h_t (bf16 hi/lo) + out
#pragma unroll
        for (int rr = 0; rr < 2; rr++) {
            int e  = tid + rr * 256;
            int b  = e >> 3;
            int j  = e & 7;
            float iv = gateA[(0 * 8 + j) * 66 + b] + gateB[(0 * 8 + j) * 66 + b];
            float fv = gateA[(1 * 8 + j) * 66 + b] + gateB[(1 * 8 + j) * 66 + b];
            float gv = gateA[(2 * 8 + j) * 66 + b] + gateB[(2 * 8 + j) * 66 + b];
            float ov = gateA[(3 * 8 + j) * 66 + b] + gateB[(3 * 8 + j) * 66 + b];
            iv = fsigmoid(iv);
            fv = fsigmoid(fv);
            ov = fsigmoid(ov);
            gv = ftanh_(gv);
            float cn = fv * c_sm[e] + iv * gv;
            c_sm[e] = cn;
            float hn = ov * ftanh_(cn);
            __nv_bfloat16 hi = __float2bfloat16(hn);
            g_hbf[d][pw][0][b][hs0 + j] = hi;
            g_hbf[d][pw][1][b][hs0 + j] = __float2bfloat16(hn - __bfloat162float(hi));
            out[((size_t)b * SS + t) * (2 * HH) + d * HH + hs0 + j] = hn;
        }

        grid_barrier(d);
    }
}

// ---------------------------------------------------------------------------
// Launch
// ---------------------------------------------------------------------------
extern "C" void kernel_launch(void* const* d_in, const int* in_sizes, int n_in,
                              void* d_out, int out_size)
{
    (void)in_sizes; (void)n_in; (void)out_size;
    const float* x = (const float*)d_in[0];

    Ptrs p;
    for (int d = 0; d < 2; d++)
        for (int g = 0; g < 4; g++) {
            p.W[d][g]    = (const float*)d_in[1 + d * 8 + 2 * g];
            p.bias[d][g] = (const float*)d_in[1 + d * 8 + 2 * g + 1];
        }

    cudaFuncSetAttribute(lstm_rec_mma_kernel,
                         cudaFuncAttributeMaxDynamicSharedMemorySize,
                         RB_SMEM_BYTES);
    cudaFuncSetAttribute(proj_mma_kernel,
                         cudaFuncAttributeMaxDynamicSharedMemorySize,
                         PJ_SMEM_BYTES);

    split_x_kernel<<<512, 256>>>(x);
    dim3 wgrid(16, 16, 8);
    split_wt_kernel<<<wgrid, 256>>>(p);

    dim3 pgrid(16, 128, 2);
    proj_mma_kernel<<<pgrid, 256, PJ_SMEM_BYTES>>>(p);

    lstm_rec_mma_kernel<<<128, 256, RB_SMEM_BYTES>>>((float*)d_out, p);
}